// round 3
// baseline (speedup 1.0000x reference)
#include <cuda_runtime.h>
#include <math.h>

#define NN 10000
#define NF 128
#define NH 64
#define MAXNNZ 2000000
#define CAP 16

// ---------------- scratch (device globals, no allocation) ----------------
__device__ float g_A[NN * NH];   // P buffer (outcome path)
__device__ float g_B[NN * NH];   // P buffer (treatment path)
__device__ float g_C[NN * NH];   // rep buffer (outcome path)
__device__ float g_D[NN * NH];   // rep buffer (treatment path)

__device__ int   g_rowbase[NN];
__device__ int   g_rownnz[NN];
__device__ int   g_cols[MAXNNZ];
__device__ float g_vals[MAXNNZ];
__device__ int   g_top;

__device__ float g_ssrc[NN];
__device__ float g_sdst[NN];
__device__ float g_part[64 * NH];
__device__ float g_Sall[NH];

// ---------------- reset ----------------
__global__ void k_reset() { g_top = 0; }

// ---------------- sparsify: dense adj -> per-row compacted (col,val) ----------------
__global__ void k_sparsify(const float* __restrict__ adj) {
    int row = blockIdx.x;
    const float4* rp = (const float4*)(adj + (size_t)row * NN);
    __shared__ int   scols[256 * CAP];
    __shared__ float svals[256 * CAP];
    __shared__ int   wsum[8];
    __shared__ int   sbase;

    int t = threadIdx.x;
    int lane = t & 31, wid = t >> 5;
    int c = 0;
    // NN/4 = 2500 float4 per row, strided coalesced
    for (int j = t; j < NN / 4; j += 256) {
        float4 v = rp[j];
        int cb = j * 4;
        if (v.x != 0.f && c < CAP) { scols[t * CAP + c] = cb + 0; svals[t * CAP + c] = v.x; c++; }
        if (v.y != 0.f && c < CAP) { scols[t * CAP + c] = cb + 1; svals[t * CAP + c] = v.y; c++; }
        if (v.z != 0.f && c < CAP) { scols[t * CAP + c] = cb + 2; svals[t * CAP + c] = v.z; c++; }
        if (v.w != 0.f && c < CAP) { scols[t * CAP + c] = cb + 3; svals[t * CAP + c] = v.w; c++; }
    }
    // warp inclusive scan of counts
    int v = c;
    #pragma unroll
    for (int d = 1; d < 32; d <<= 1) {
        int n = __shfl_up_sync(0xffffffffu, v, d);
        if (lane >= d) v += n;
    }
    if (lane == 31) wsum[wid] = v;
    __syncthreads();
    int wbase = 0;
    #pragma unroll
    for (int i = 0; i < 8; i++) wbase += (i < wid) ? wsum[i] : 0;
    int excl = wbase + v - c;
    if (t == 0) {
        int tot = 0;
        #pragma unroll
        for (int i = 0; i < 8; i++) tot += wsum[i];
        int b = atomicAdd(&g_top, tot);
        g_rowbase[row] = b;
        g_rownnz[row]  = tot;
        sbase = b;
    }
    __syncthreads();
    int dst = sbase + excl;
    for (int i = 0; i < c; i++) {
        g_cols[dst + i] = scols[t * CAP + i];
        g_vals[dst + i] = svals[t * CAP + i];
    }
}

// ---------------- dense GEMM: [NN,K] @ [K,64] for both o/t paths ----------------
// block (64,4): 16 rows per block, thread (tx,ty) -> col tx, rows ty*4..ty*4+3
template <int K>
__global__ void k_gemm(const float* __restrict__ X0, const float* __restrict__ X1,
                       const float* __restrict__ W0, const float* __restrict__ W1,
                       int src_global) {
    __shared__ float Ws[K * 64];
    __shared__ float xs[16 * K];
    int tx = threadIdx.x, ty = threadIdx.y;
    int tid = ty * 64 + tx;
    int m = blockIdx.y;
    const float* W = m ? W1 : W0;
    const float* X = src_global ? (m ? g_D : g_C) : (m ? X1 : X0);
    float* out = m ? g_B : g_A;

    for (int i = tid; i < K * 64; i += 256) Ws[i] = W[i];
    int r0 = blockIdx.x * 16;
    for (int i = tid; i < 16 * K; i += 256) xs[i] = X[(size_t)r0 * K + i];
    __syncthreads();

    float acc[4] = {0.f, 0.f, 0.f, 0.f};
    #pragma unroll 4
    for (int k = 0; k < K; k++) {
        float w = Ws[k * 64 + tx];
        #pragma unroll
        for (int i = 0; i < 4; i++) acc[i] += xs[(ty * 4 + i) * K + k] * w;
    }
    #pragma unroll
    for (int i = 0; i < 4; i++) out[(size_t)(r0 + ty * 4 + i) * 64 + tx] = acc[i];
}

// ---------------- SpMM + bias + relu: rep = relu(adj @ P + b) ----------------
__global__ void k_spmm(const float* __restrict__ bA, const float* __restrict__ bB) {
    int row = blockIdx.x;
    int m = blockIdx.y;
    const float* P = m ? g_B : g_A;
    const float* b = m ? bB : bA;
    float* out = m ? g_D : g_C;
    int base = g_rowbase[row], nnz = g_rownnz[row];
    int h = threadIdx.x;
    float acc = 0.f;
    for (int e = 0; e < nnz; e++) {
        int cc = g_cols[base + e];
        float vv = g_vals[base + e];
        acc += vv * P[(size_t)cc * 64 + h];
    }
    acc += b[h];
    out[(size_t)row * 64 + h] = acc > 0.f ? acc : 0.f;
}

// ---------------- attention scores s_src/s_dst ----------------
__global__ void k_scores(const float* __restrict__ a) {
    int row = blockIdx.x;
    int h = threadIdx.x;
    float vo = g_C[(size_t)row * 64 + h];
    float vt = g_D[(size_t)row * 64 + h];
    __shared__ float rs[64], rd[64];
    rs[h] = vo * a[h]       + vt * a[64 + h];
    rd[h] = vo * a[128 + h] + vt * a[192 + h];
    __syncthreads();
    for (int s = 32; s > 0; s >>= 1) {
        if (h < s) { rs[h] += rs[h + s]; rd[h] += rd[h + s]; }
        __syncthreads();
    }
    if (h == 0) { g_ssrc[row] = rs[0]; g_sdst[row] = rd[0]; }
}

// ---------------- column sum of rep_t (deterministic 2-stage) ----------------
__global__ void k_colsum_part() {
    int b = blockIdx.x;   // 64 blocks
    int h = threadIdx.x;  // 64 threads
    int r0 = b * 157;
    int r1 = r0 + 157; if (r1 > NN) r1 = NN;
    float acc = 0.f;
    for (int r = r0; r < r1; r++) acc += g_D[(size_t)r * 64 + h];
    g_part[b * 64 + h] = acc;
}
__global__ void k_colsum_comb() {
    int h = threadIdx.x;
    float acc = 0.f;
    for (int b = 0; b < 64; b++) acc += g_part[b * 64 + h];
    g_Sall[h] = acc;
}

// ---------------- attention row (analytic dense softmax over sparse scores) ----------------
__global__ void k_att(float* __restrict__ dout) {
    int row = blockIdx.x;
    int h = threadIdx.x;
    int base = g_rowbase[row], nnz = g_rownnz[row];
    float si = g_ssrc[row];
    __shared__ float red[64];

    float lm = -1e30f;
    for (int e = h; e < nnz; e += 64)
        lm = fmaxf(lm, si + g_sdst[g_cols[base + e]]);
    red[h] = lm;
    __syncthreads();
    for (int s = 32; s > 0; s >>= 1) {
        if (h < s) red[h] = fmaxf(red[h], red[h + s]);
        __syncthreads();
    }
    float m = fmaxf(red[0], 0.f);   // non-edges contribute att = 0

    float accW = 0.f, accR = 0.f, sw = 0.f;
    for (int e = 0; e < nnz; e++) {
        int cc = g_cols[base + e];
        float w = __expf(si + g_sdst[cc] - m);
        float rv = g_D[(size_t)cc * 64 + h];
        accW += w * rv;
        accR += rv;
        sw += w;
    }
    float em = __expf(-m);
    float denom = (float)(NN - nnz) * em + sw;
    float val = (em * (g_Sall[h] - accR) + accW) / denom + g_C[(size_t)row * 64 + h];
    dout[10000 + (size_t)row * 64 + h] = val;   // rep_out region
}

// ---------------- heads: y, treatment ----------------
__global__ void k_heads(const int* __restrict__ t,
                        const float* __restrict__ W000, const float* __restrict__ b000,
                        const float* __restrict__ W001, const float* __restrict__ b001,
                        const float* __restrict__ W100, const float* __restrict__ b100,
                        const float* __restrict__ W101, const float* __restrict__ b101,
                        const float* __restrict__ Wo0,  const float* __restrict__ bo0,
                        const float* __restrict__ Wo1,  const float* __restrict__ bo1,
                        const float* __restrict__ Wpp,  const float* __restrict__ bpp,
                        const float* __restrict__ Wpp2, const float* __restrict__ bpp2,
                        float* __restrict__ dout) {
    int row = blockIdx.x;
    int h = threadIdx.x;
    __shared__ float r[64], rt_s[64], h1[64], h2[64], red[64], sy0, sy1;

    r[h]    = dout[10000 + (size_t)row * 64 + h];
    rt_s[h] = g_D[(size_t)row * 64 + h];
    __syncthreads();

    // ---- y0 path
    float acc = 0.f;
    for (int k = 0; k < 64; k++) acc += r[k] * W000[k * 64 + h];
    acc += b000[h];
    h1[h] = acc > 0.f ? acc : 0.f;
    __syncthreads();
    acc = 0.f;
    for (int k = 0; k < 64; k++) acc += h1[k] * W001[k * 64 + h];
    acc += b001[h];
    h2[h] = acc > 0.f ? acc : 0.f;
    __syncthreads();
    red[h] = h2[h] * Wo0[h];
    __syncthreads();
    for (int s = 32; s > 0; s >>= 1) { if (h < s) red[h] += red[h + s]; __syncthreads(); }
    if (h == 0) sy0 = red[0] + bo0[0];
    __syncthreads();

    // ---- y1 path
    acc = 0.f;
    for (int k = 0; k < 64; k++) acc += r[k] * W100[k * 64 + h];
    acc += b100[h];
    h1[h] = acc > 0.f ? acc : 0.f;
    __syncthreads();
    acc = 0.f;
    for (int k = 0; k < 64; k++) acc += h1[k] * W101[k * 64 + h];
    acc += b101[h];
    h2[h] = acc > 0.f ? acc : 0.f;
    __syncthreads();
    red[h] = h2[h] * Wo1[h];
    __syncthreads();
    for (int s = 32; s > 0; s >>= 1) { if (h < s) red[h] += red[h + s]; __syncthreads(); }
    if (h == 0) sy1 = red[0] + bo1[0];
    __syncthreads();

    // ---- treatment head (no relu between Wpp and Wpp2)
    acc = 0.f;
    for (int k = 0; k < 64; k++) acc += rt_s[k] * Wpp[k * 64 + h];
    acc += bpp[h];
    h1[h] = acc;
    __syncthreads();
    if (h < 2) {
        float z = 0.f;
        for (int k = 0; k < 64; k++) z += h1[k] * Wpp2[k * 2 + h];
        z += bpp2[h];
        dout[650000 + (size_t)row * 2 + h] = 1.f / (1.f + __expf(-z));
    }
    if (h == 0) dout[row] = (t[row] > 0) ? sy1 : sy0;
}

// ---------------- launch ----------------
extern "C" void kernel_launch(void* const* d_in, const int* in_sizes, int n_in,
                              void* d_out, int out_size) {
    const float* x    = (const float*)d_in[0];
    const float* adj  = (const float*)d_in[1];
    const int*   t    = (const int*)d_in[2];
    const float* Wg0  = (const float*)d_in[3];
    const float* bg0  = (const float*)d_in[4];
    const float* Wg1  = (const float*)d_in[5];
    const float* bg1  = (const float*)d_in[6];
    const float* Wt0  = (const float*)d_in[7];
    const float* bt0  = (const float*)d_in[8];
    const float* Wt1  = (const float*)d_in[9];
    const float* bt1  = (const float*)d_in[10];
    const float* W000 = (const float*)d_in[11];
    const float* b000 = (const float*)d_in[12];
    const float* W001 = (const float*)d_in[13];
    const float* b001 = (const float*)d_in[14];
    const float* W100 = (const float*)d_in[15];
    const float* b100 = (const float*)d_in[16];
    const float* W101 = (const float*)d_in[17];
    const float* b101 = (const float*)d_in[18];
    const float* Wo0  = (const float*)d_in[19];
    const float* bo0  = (const float*)d_in[20];
    const float* Wo1  = (const float*)d_in[21];
    const float* bo1  = (const float*)d_in[22];
    const float* Wpp  = (const float*)d_in[23];
    const float* bpp  = (const float*)d_in[24];
    const float* Wpp2 = (const float*)d_in[25];
    const float* bpp2 = (const float*)d_in[26];
    const float* a    = (const float*)d_in[27];
    float* out = (float*)d_out;

    k_reset<<<1, 1>>>();
    k_sparsify<<<NN, 256>>>(adj);

    dim3 tB(64, 4);
    // layer 1: P = x @ Wg0 / x @ Wt0
    k_gemm<128><<<dim3(NN / 16, 2), tB>>>(x, x, Wg0, Wt0, 0);
    // rep1 = relu(adj @ P + b0)
    k_spmm<<<dim3(NN, 2), 64>>>(bg0, bt0);
    // layer 2: P = rep1 @ Wg1 / rep1 @ Wt1
    k_gemm<64><<<dim3(NN / 16, 2), tB>>>(nullptr, nullptr, Wg1, Wt1, 1);
    // rep = relu(adj @ P + b1)
    k_spmm<<<dim3(NN, 2), 64>>>(bg1, bt1);

    k_scores<<<NN, 64>>>(a);
    k_colsum_part<<<64, 64>>>();
    k_colsum_comb<<<1, 64>>>();
    k_att<<<NN, 64>>>(out);
    k_heads<<<NN, 64>>>(t, W000, b000, W001, b001, W100, b100, W101, b101,
                        Wo0, bo0, Wo1, bo1, Wpp, bpp, Wpp2, bpp2, out);
}